// round 16
// baseline (speedup 1.0000x reference)
#include <cuda_runtime.h>
#include <cuda_fp16.h>

// DigitCaps dynamic routing, TWO-KERNEL version, fp16 u_hat scratch,
// small-CTA high-ILP routing kernel.
// k1: u_hat = einsum('bni,knio->kbno') smem-tiled register-blocked GEMM,
//     fp16 output to __device__ scratch, layout [k][b][p(=o>>2)][n] (uint2).
// k2: one CTA per (k,b), 128 threads, 6 CTAs/SM. u_hat slice kept fp16 in
//     smem (36.9 KB); converted to fp32 at use. 9 n per thread -> 9
//     independent LDS->dot->exp chains (latency hiding). Single-pass softmax
//     (no max-subtract: logits bounded |b| < ~40 << 88). All math fp32.
//
// u:   [B=256, N=1152, IN_C=8]              f32
// W:   [K=10,  N=1152, IN_C=8, OUT_C=16]    f32
// out: [K, B, 1, 1, OUT_C]                  f32

constexpr int KDIM = 10;
constexpr int BDIM = 256;
constexpr int NDIM = 1152;
constexpr int INC  = 8;
constexpr int OUTC = 16;

// ---------- scratch: u_hat fp16, [k][b][p][n] as uint2 (4 halves) ----------
__device__ uint2 uhat_g[(size_t)KDIM * BDIM * 4 * NDIM];

// ======================= kernel 1: u_hat GEMM ==========================
constexpr int K1_THREADS = 512;
constexpr int BT = 128;            // b-tile
constexpr int NC = 16;             // n-chunk
constexpr int URow = 132;          // padded u_sm row (16n*8i + 4)
constexpr int WRow = 132;          // padded w_sm row (8i*16o + 4)

struct SM1 {
    alignas(16) float u_sm[BT * URow];   // 67584 B
    alignas(16) float w_sm[NC * WRow];   //  8448 B
};

__global__ void __launch_bounds__(K1_THREADS, 2)
uhat_kernel(const float* __restrict__ u, const float* __restrict__ W)
{
    extern __shared__ char smem_raw[];
    SM1* sm = reinterpret_cast<SM1*>(smem_raw);
    const int t  = threadIdx.x;
    const int n0 = blockIdx.x * NC;
    const int b0 = blockIdx.y * BT;
    const int k  = blockIdx.z;

    // load W chunk: W[k][n0..+16][8][16] = 512 float4, one per thread
    {
        const int n = t >> 5, idx = t & 31;
        float4 v = *(const float4*)(W + ((size_t)k * NDIM + n0 + n) * 128 + idx * 4);
        *(float4*)&sm->w_sm[n * WRow + idx * 4] = v;
    }
    // load u tile: u[b0..+128][n0..+16][8] = 4096 float4, 8 per thread
#pragma unroll
    for (int r = 0; r < 8; r++) {
        const int f = t + K1_THREADS * r;
        const int b = f >> 5, idx = f & 31;
        float4 v = *(const float4*)(u + ((size_t)(b0 + b) * NDIM + n0) * INC + idx * 4);
        *(float4*)&sm->u_sm[b * URow + idx * 4] = v;
    }
    __syncthreads();

    const int n  = t & 15;
    const int oq = (t >> 4) & 3;
    const int bb = t >> 6;            // 0..7, each handles 16 b's

    // W quad for this (n, oq): 8 i-rows of 4 o's, register-resident
    float4 wq[INC];
#pragma unroll
    for (int i = 0; i < INC; i++)
        wq[i] = *(const float4*)&sm->w_sm[n * WRow + i * OUTC + oq * 4];

    uint2* dst_base = uhat_g +
        ((size_t)(k * BDIM + b0) * 4 + oq) * NDIM + (n0 + n);

#pragma unroll 4
    for (int bi = 0; bi < 16; bi++) {
        const int b = bb * 16 + bi;
        float4 ua = *(const float4*)&sm->u_sm[b * URow + n * INC];      // i 0..3
        float4 ub = *(const float4*)&sm->u_sm[b * URow + n * INC + 4];  // i 4..7
        float4 acc;
        acc.x = ua.x * wq[0].x; acc.y = ua.x * wq[0].y;
        acc.z = ua.x * wq[0].z; acc.w = ua.x * wq[0].w;
        acc.x = fmaf(ua.y, wq[1].x, acc.x); acc.y = fmaf(ua.y, wq[1].y, acc.y);
        acc.z = fmaf(ua.y, wq[1].z, acc.z); acc.w = fmaf(ua.y, wq[1].w, acc.w);
        acc.x = fmaf(ua.z, wq[2].x, acc.x); acc.y = fmaf(ua.z, wq[2].y, acc.y);
        acc.z = fmaf(ua.z, wq[2].z, acc.z); acc.w = fmaf(ua.z, wq[2].w, acc.w);
        acc.x = fmaf(ua.w, wq[3].x, acc.x); acc.y = fmaf(ua.w, wq[3].y, acc.y);
        acc.z = fmaf(ua.w, wq[3].z, acc.z); acc.w = fmaf(ua.w, wq[3].w, acc.w);
        acc.x = fmaf(ub.x, wq[4].x, acc.x); acc.y = fmaf(ub.x, wq[4].y, acc.y);
        acc.z = fmaf(ub.x, wq[4].z, acc.z); acc.w = fmaf(ub.x, wq[4].w, acc.w);
        acc.x = fmaf(ub.y, wq[5].x, acc.x); acc.y = fmaf(ub.y, wq[5].y, acc.y);
        acc.z = fmaf(ub.y, wq[5].z, acc.z); acc.w = fmaf(ub.y, wq[5].w, acc.w);
        acc.x = fmaf(ub.z, wq[6].x, acc.x); acc.y = fmaf(ub.z, wq[6].y, acc.y);
        acc.z = fmaf(ub.z, wq[6].z, acc.z); acc.w = fmaf(ub.z, wq[6].w, acc.w);
        acc.x = fmaf(ub.w, wq[7].x, acc.x); acc.y = fmaf(ub.w, wq[7].y, acc.y);
        acc.z = fmaf(ub.w, wq[7].z, acc.z); acc.w = fmaf(ub.w, wq[7].w, acc.w);
        // fp16 pack: 4 halves = uint2
        __half2 h01 = __float22half2_rn(make_float2(acc.x, acc.y));
        __half2 h23 = __float22half2_rn(make_float2(acc.z, acc.w));
        uint2 pack;
        pack.x = *reinterpret_cast<unsigned int*>(&h01);
        pack.y = *reinterpret_cast<unsigned int*>(&h23);
        // [k][b][oq][n]; b stride = 4*NDIM uint2
        dst_base[(size_t)b * 4 * NDIM] = pack;
    }
}

// ======================= kernel 2: routing =============================
constexpr int K2_THREADS = 128;            // 4 warps
constexpr int K2_WARPS   = K2_THREADS / 32;
constexpr int NPH2 = NDIM / K2_THREADS;    // 9 n per thread

struct SM2 {
    alignas(16) uint2 uh2[4 * NDIM];       // fp16 u_hat [p][n]: 36864 B
    alignas(16) float vec[K2_WARPS * OUTC];
    float red[K2_WARPS];
    alignas(16) float v[OUTC];
};

__device__ __forceinline__ float dot4_(float4 a, float4 b) {
    return fmaf(a.x, b.x, fmaf(a.y, b.y, fmaf(a.z, b.z, a.w * b.w)));
}
__device__ __forceinline__ float4 cvt_h4(uint2 raw) {
    __half2 h01 = *reinterpret_cast<__half2*>(&raw.x);
    __half2 h23 = *reinterpret_cast<__half2*>(&raw.y);
    float2 f01 = __half22float2(h01);
    float2 f23 = __half22float2(h23);
    return make_float4(f01.x, f01.y, f23.x, f23.y);
}

__global__ void __launch_bounds__(K2_THREADS, 6)
routing_kernel(float* __restrict__ out)
{
    extern __shared__ char smem_raw[];
    SM2* sm = reinterpret_cast<SM2*>(smem_raw);
    const int kb   = blockIdx.x;           // k*256 + b
    const int t    = threadIdx.x;
    const int w    = t >> 5;
    const int lane = t & 31;

    // ---- copy fp16 slice to smem + iteration-0 accumulation (fp32) ----
    const uint2* src = uhat_g + (size_t)kb * 4 * NDIM;
    float acc[OUTC];
#pragma unroll
    for (int oo = 0; oo < OUTC; oo++) acc[oo] = 0.0f;

#pragma unroll
    for (int p = 0; p < 4; p++) {
#pragma unroll
        for (int j = 0; j < NPH2; j++) {
            const int idx = p * NDIM + t + K2_THREADS * j;
            uint2 raw = src[idx];
            sm->uh2[idx] = raw;
            float4 val = cvt_h4(raw);
            acc[p * 4 + 0] += val.x;
            acc[p * 4 + 1] += val.y;
            acc[p * 4 + 2] += val.z;
            acc[p * 4 + 3] += val.w;
        }
    }

    // 16-value butterfly over 32 lanes (16 shfl); channel o -> lanes 2o,2o+1
#pragma unroll
    for (int d = 16, c = 16; d >= 2; d >>= 1, c >>= 1) {
        const bool up = (lane & d) != 0;
        const int half = c >> 1;
#pragma unroll
        for (int i = 0; i < half; i++) {
            float send = up ? acc[i] : acc[i + half];
            float keep = up ? acc[i + half] : acc[i];
            acc[i] = keep + __shfl_xor_sync(0xffffffffu, send, d);
        }
    }
    acc[0] += __shfl_xor_sync(0xffffffffu, acc[0], 1);
    if ((lane & 1) == 0) sm->vec[w * OUTC + (lane >> 1)] = acc[0];
    __syncthreads();   // also orders uh2 STS before routing LDS

    // ---- squash helper (warp 0) ----
    auto squash_store = [&](bool use_se, bool write_out) {
        if (t < 32) {
            const int oo = t & 15;         // both 16-lane halves identical
            float s = 0.0f, se = 0.0f;
#pragma unroll
            for (int ww = 0; ww < K2_WARPS; ww++) {
                s += sm->vec[ww * OUTC + oo];
                if (use_se) se += sm->red[ww];
            }
            if (!use_se) se = (float)NDIM;
            s /= se;
            float sq = s * s;
#pragma unroll
            for (int d = 1; d < 16; d <<= 1)
                sq += __shfl_xor_sync(0xffffffffu, sq, d);
            float f  = sqrtf(sq) / (1.0f + sq);
            float vv = s * f;
            if (t < OUTC) {
                sm->v[oo] = vv;
                if (write_out) out[(size_t)kb * OUTC + oo] = vv;
            }
        }
        __syncthreads();
    };

    squash_store(false, false);            // iteration 0

    float aold[NPH2];                      // routing logits in registers
#pragma unroll
    for (int q = 0; q < NPH2; q++) aold[q] = 0.0f;

#pragma unroll 1
    for (int it = 1; it < 3; it++) {
        float4 v0 = *(const float4*)&sm->v[0];
        float4 v1 = *(const float4*)&sm->v[4];
        float4 v2 = *(const float4*)&sm->v[8];
        float4 v3 = *(const float4*)&sm->v[12];

        float se = 0.0f;
        float ps[OUTC];
#pragma unroll
        for (int oo = 0; oo < OUTC; oo++) ps[oo] = 0.0f;

#pragma unroll
        for (int q = 0; q < NPH2; q++) {
            const int n = t + q * K2_THREADS;
            float4 h0 = cvt_h4(sm->uh2[0 * NDIM + n]);
            float4 h1 = cvt_h4(sm->uh2[1 * NDIM + n]);
            float4 h2 = cvt_h4(sm->uh2[2 * NDIM + n]);
            float4 h3 = cvt_h4(sm->uh2[3 * NDIM + n]);
            float a = (dot4_(h0, v0) + dot4_(h1, v1)) +
                      (dot4_(h2, v2) + dot4_(h3, v3)) + aold[q];
            aold[q] = a;
            float e = __expf(a);           // no max-subtract: |a| << 88
            se += e;
            ps[0]  = fmaf(e, h0.x, ps[0]);
            ps[1]  = fmaf(e, h0.y, ps[1]);
            ps[2]  = fmaf(e, h0.z, ps[2]);
            ps[3]  = fmaf(e, h0.w, ps[3]);
            ps[4]  = fmaf(e, h1.x, ps[4]);
            ps[5]  = fmaf(e, h1.y, ps[5]);
            ps[6]  = fmaf(e, h1.z, ps[6]);
            ps[7]  = fmaf(e, h1.w, ps[7]);
            ps[8]  = fmaf(e, h2.x, ps[8]);
            ps[9]  = fmaf(e, h2.y, ps[9]);
            ps[10] = fmaf(e, h2.z, ps[10]);
            ps[11] = fmaf(e, h2.w, ps[11]);
            ps[12] = fmaf(e, h3.x, ps[12]);
            ps[13] = fmaf(e, h3.y, ps[13]);
            ps[14] = fmaf(e, h3.z, ps[14]);
            ps[15] = fmaf(e, h3.w, ps[15]);
        }

        // 16-value butterfly over 32 lanes (16 shfl); channel o -> lanes 2o
#pragma unroll
        for (int d = 16, c = 16; d >= 2; d >>= 1, c >>= 1) {
            const bool up = (lane & d) != 0;
            const int half = c >> 1;
#pragma unroll
            for (int i = 0; i < half; i++) {
                float send = up ? ps[i] : ps[i + half];
                float keep = up ? ps[i + half] : ps[i];
                ps[i] = keep + __shfl_xor_sync(0xffffffffu, send, d);
            }
        }
        ps[0] += __shfl_xor_sync(0xffffffffu, ps[0], 1);
        if ((lane & 1) == 0) sm->vec[w * OUTC + (lane >> 1)] = ps[0];

#pragma unroll
        for (int d = 1; d < 32; d <<= 1)
            se += __shfl_xor_sync(0xffffffffu, se, d);
        if (lane == 0) sm->red[w] = se;

        __syncthreads();
        squash_store(true, it == 2);
    }
}

// ============================ launch ===================================
extern "C" void kernel_launch(void* const* d_in, const int* in_sizes, int n_in,
                              void* d_out, int out_size)
{
    const float* u = (const float*)d_in[0];
    const float* W = (const float*)d_in[1];
    // defensive: identify by element count (u: 2359296, W: 1474560)
    if (n_in >= 2 && in_sizes[0] == KDIM * NDIM * INC * OUTC &&
        in_sizes[1] == BDIM * NDIM * INC) {
        const float* tmp = u; u = W; W = tmp;
    }
    float* out = (float*)d_out;

    cudaFuncSetAttribute(uhat_kernel,
                         cudaFuncAttributeMaxDynamicSharedMemorySize,
                         (int)sizeof(SM1));
    cudaFuncSetAttribute(routing_kernel,
                         cudaFuncAttributeMaxDynamicSharedMemorySize,
                         (int)sizeof(SM2));

    dim3 g1(NDIM / NC, BDIM / BT, KDIM);   // (72, 2, 10)
    uhat_kernel<<<g1, K1_THREADS, sizeof(SM1)>>>(u, W);
    routing_kernel<<<KDIM * BDIM, K2_THREADS, sizeof(SM2)>>>(out);
}